// round 2
// baseline (speedup 1.0000x reference)
#include <cuda_runtime.h>
#include <cuda_bf16.h>
#include <math.h>

// Problem constants
#define Bc 2
#define Nc 2048
#define Dc 1024
#define Hc 16
#define HDc 64
#define BH (Bc * Hc)          // 32
#define MROWS (Bc * Nc)       // 4096
#define OUT_ELEMS ((size_t)Bc * Nc * Dc)              // 4,194,304
#define A_ELEMS ((size_t)Bc * Hc * Nc * Nc)           // 134,217,728

// Scratch (static device memory — allowed; no runtime allocation)
__device__ float g_Q[MROWS * Dc];
__device__ float g_K[MROWS * Dc];
__device__ float g_V[MROWS * Dc];
__device__ float g_Vt[MROWS * Dc];

// ---------------------------------------------------------------------------
// GEMM: C[M,N] = X[M,K] @ W[N,K]^T + bias[N]   (all row-major, K contiguous)
// 32x32 tile, 16x16 threads, 2x2 per thread.
// ---------------------------------------------------------------------------
__global__ void gemm_xwT(const float* __restrict__ X, const float* __restrict__ W,
                         const float* __restrict__ bias, float* __restrict__ C,
                         int M, int N, int K) {
    __shared__ float As[32][33];
    __shared__ float Bs[32][33];
    const int tx = threadIdx.x, ty = threadIdx.y;   // 16x16
    const int tid = ty * 16 + tx;
    const int row0 = blockIdx.y * 32;
    const int col0 = blockIdx.x * 32;

    float acc00 = 0.f, acc01 = 0.f, acc10 = 0.f, acc11 = 0.f;

    for (int kt = 0; kt < K; kt += 32) {
        #pragma unroll
        for (int l = tid; l < 32 * 32; l += 256) {
            int r = l >> 5, c = l & 31;
            As[r][c] = X[(size_t)(row0 + r) * K + kt + c];
            Bs[r][c] = W[(size_t)(col0 + r) * K + kt + c];
        }
        __syncthreads();
        #pragma unroll
        for (int kk = 0; kk < 32; kk++) {
            float a0 = As[2 * ty][kk];
            float a1 = As[2 * ty + 1][kk];
            float b0 = Bs[2 * tx][kk];
            float b1 = Bs[2 * tx + 1][kk];
            acc00 = fmaf(a0, b0, acc00);
            acc01 = fmaf(a0, b1, acc01);
            acc10 = fmaf(a1, b0, acc10);
            acc11 = fmaf(a1, b1, acc11);
        }
        __syncthreads();
    }

    const int r0 = row0 + 2 * ty;
    const int c0 = col0 + 2 * tx;
    float bia0 = bias[c0], bia1 = bias[c0 + 1];
    C[(size_t)r0 * N + c0]           = acc00 + bia0;
    C[(size_t)r0 * N + c0 + 1]       = acc01 + bia1;
    C[(size_t)(r0 + 1) * N + c0]     = acc10 + bia0;
    C[(size_t)(r0 + 1) * N + c0 + 1] = acc11 + bia1;
}

// ---------------------------------------------------------------------------
// S = scale * Q_h @ K_h^T  per (b,h).  Q,K stored [B*N, D] with head slice.
// Block: 32(i) x 32(j) tile, z = b*H + h.  K-dim = 64.
// ---------------------------------------------------------------------------
__global__ void qk_kernel(const float* __restrict__ Q, const float* __restrict__ K,
                          float* __restrict__ A) {
    __shared__ float Qs[32][65];
    __shared__ float Ks[32][65];
    const int bh = blockIdx.z;
    const int b = bh / Hc, h = bh % Hc;
    const int i0 = blockIdx.y * 32;
    const int j0 = blockIdx.x * 32;
    const int tx = threadIdx.x, ty = threadIdx.y;
    const int tid = ty * 16 + tx;

    const float* Qb = Q + (size_t)b * Nc * Dc + h * HDc;
    const float* Kb = K + (size_t)b * Nc * Dc + h * HDc;

    #pragma unroll
    for (int l = tid; l < 32 * 64; l += 256) {
        int r = l >> 6, c = l & 63;
        Qs[r][c] = Qb[(size_t)(i0 + r) * Dc + c];
        Ks[r][c] = Kb[(size_t)(j0 + r) * Dc + c];
    }
    __syncthreads();

    float acc00 = 0.f, acc01 = 0.f, acc10 = 0.f, acc11 = 0.f;
    #pragma unroll
    for (int kk = 0; kk < 64; kk++) {
        float a0 = Qs[2 * ty][kk];
        float a1 = Qs[2 * ty + 1][kk];
        float b0 = Ks[2 * tx][kk];
        float b1 = Ks[2 * tx + 1][kk];
        acc00 = fmaf(a0, b0, acc00);
        acc01 = fmaf(a0, b1, acc01);
        acc10 = fmaf(a1, b0, acc10);
        acc11 = fmaf(a1, b1, acc11);
    }

    const float scale = 0.125f;  // 1/sqrt(64)
    float* Ab = A + (size_t)bh * Nc * Nc;
    const int i = i0 + 2 * ty;
    const int j = j0 + 2 * tx;
    Ab[(size_t)i * Nc + j]           = acc00 * scale;
    Ab[(size_t)i * Nc + j + 1]       = acc01 * scale;
    Ab[(size_t)(i + 1) * Nc + j]     = acc10 * scale;
    Ab[(size_t)(i + 1) * Nc + j + 1] = acc11 * scale;
}

// ---------------------------------------------------------------------------
// Row softmax in place. One block per row of 2048.
// ---------------------------------------------------------------------------
__global__ void softmax_kernel(float* __restrict__ A) {
    __shared__ float buf[2048];
    __shared__ float red[256];
    float* p = A + (size_t)blockIdx.x * Nc;
    const int t = threadIdx.x;

    float m = -1e30f;
    for (int c = t; c < Nc; c += 256) {
        float v = p[c];
        buf[c] = v;
        m = fmaxf(m, v);
    }
    red[t] = m;
    __syncthreads();
    for (int s = 128; s > 0; s >>= 1) {
        if (t < s) red[t] = fmaxf(red[t], red[t + s]);
        __syncthreads();
    }
    const float mx = red[0];
    __syncthreads();

    float sum = 0.f;
    for (int c = t; c < Nc; c += 256) {
        float e = __expf(buf[c] - mx);
        buf[c] = e;
        sum += e;
    }
    red[t] = sum;
    __syncthreads();
    for (int s = 128; s > 0; s >>= 1) {
        if (t < s) red[t] += red[t + s];
        __syncthreads();
    }
    const float inv = 1.f / red[0];

    for (int c = t; c < Nc; c += 256) p[c] = buf[c] * inv;
}

// ---------------------------------------------------------------------------
// Vh = A @ V_h per (b,h), written into [B,N,D] layout (head-interleaved).
// Block: 32(i) x 64(d) tile; 16x16 threads, 2x4 per thread.
// ---------------------------------------------------------------------------
__global__ void av_kernel(const float* __restrict__ A, const float* __restrict__ V,
                          float* __restrict__ Vt) {
    __shared__ float As[32][33];
    __shared__ float Vs[32][65];
    const int bh = blockIdx.z;
    const int b = bh / Hc, h = bh % Hc;
    const int i0 = blockIdx.y * 32;
    const int tx = threadIdx.x, ty = threadIdx.y;
    const int tid = ty * 16 + tx;

    const float* Ab = A + (size_t)bh * Nc * Nc;
    const float* Vb = V + (size_t)b * Nc * Dc + h * HDc;

    float acc[2][4] = {};

    for (int j0 = 0; j0 < Nc; j0 += 32) {
        #pragma unroll
        for (int l = tid; l < 32 * 32; l += 256) {
            int r = l >> 5, c = l & 31;
            As[r][c] = Ab[(size_t)(i0 + r) * Nc + j0 + c];
        }
        #pragma unroll
        for (int l = tid; l < 32 * 64; l += 256) {
            int r = l >> 6, c = l & 63;
            Vs[r][c] = Vb[(size_t)(j0 + r) * Dc + c];
        }
        __syncthreads();
        #pragma unroll
        for (int jj = 0; jj < 32; jj++) {
            float a0 = As[2 * ty][jj];
            float a1 = As[2 * ty + 1][jj];
            #pragma unroll
            for (int d = 0; d < 4; d++) {
                float v = Vs[jj][tx * 4 + d];
                acc[0][d] = fmaf(a0, v, acc[0][d]);
                acc[1][d] = fmaf(a1, v, acc[1][d]);
            }
        }
        __syncthreads();
    }

    #pragma unroll
    for (int a = 0; a < 2; a++) {
        const int i = i0 + 2 * ty + a;
        float* dst = Vt + (size_t)(b * Nc + i) * Dc + h * HDc + tx * 4;
        #pragma unroll
        for (int d = 0; d < 4; d++) dst[d] = acc[a][d];
    }
}

// ---------------------------------------------------------------------------
extern "C" void kernel_launch(void* const* d_in, const int* in_sizes, int n_in,
                              void* d_out, int out_size) {
    const float* query = (const float*)d_in[0];
    const float* key   = (const float*)d_in[1];
    const float* value = (const float*)d_in[2];
    const float* Wq = (const float*)d_in[3];
    const float* bq = (const float*)d_in[4];
    const float* Wk = (const float*)d_in[5];
    const float* bk = (const float*)d_in[6];
    const float* Wv = (const float*)d_in[7];
    const float* bv = (const float*)d_in[8];
    const float* Wo = (const float*)d_in[9];
    const float* bo = (const float*)d_in[10];

    float* out = (float*)d_out;              // [B, N, D]
    float* A   = (float*)d_out + OUT_ELEMS;  // [B, H, N, N]

    float* Q;  cudaGetSymbolAddress((void**)&Q,  g_Q);
    float* K;  cudaGetSymbolAddress((void**)&K,  g_K);
    float* V;  cudaGetSymbolAddress((void**)&V,  g_V);
    float* Vt; cudaGetSymbolAddress((void**)&Vt, g_Vt);

    dim3 t16(16, 16);

    // QKV projections: [4096,1024] @ [1024,1024]^T + b
    dim3 gProj(Dc / 32, MROWS / 32);
    gemm_xwT<<<gProj, t16>>>(query, Wq, bq, Q, MROWS, Dc, Dc);
    gemm_xwT<<<gProj, t16>>>(key,   Wk, bk, K, MROWS, Dc, Dc);
    gemm_xwT<<<gProj, t16>>>(value, Wv, bv, V, MROWS, Dc, Dc);

    // S = scale * Q K^T
    dim3 gQK(Nc / 32, Nc / 32, BH);
    qk_kernel<<<gQK, t16>>>(Q, K, A);

    // softmax rows
    softmax_kernel<<<BH * Nc, 256>>>(A);

    // Vh = A V
    dim3 gAV(1, Nc / 32, BH);
    av_kernel<<<gAV, t16>>>(A, V, Vt);

    // out = Vt @ Wo^T + bo
    gemm_xwT<<<gProj, t16>>>(Vt, Wo, bo, out, MROWS, Dc, Dc);
}

// round 3
// speedup vs baseline: 2.1180x; 2.1180x over previous
#include <cuda_runtime.h>
#include <cuda_bf16.h>
#include <math.h>

// Problem constants
#define Bc 2
#define Nc 2048
#define Dc 1024
#define Hc 16
#define HDc 64
#define BH (Bc * Hc)          // 32
#define MROWS (Bc * Nc)       // 4096
#define OUT_ELEMS ((size_t)Bc * Nc * Dc)              // 4,194,304

// Scratch (static device memory — no runtime allocation)
__device__ float g_Q[MROWS * Dc];
__device__ float g_K[MROWS * Dc];
__device__ float g_V[MROWS * Dc];
__device__ float g_Vt[MROWS * Dc];

#define SM_PAD 132   // 128 + 4 pad, keeps float4 alignment (132*4 % 16 == 0)

// ---------------------------------------------------------------------------
// Projection GEMM: C[M,N] = X[M,K] @ W[N,K]^T + bias   (row-major)
// 128x128 tile, BK=16, 256 threads, 8x8 per thread.
// grid = (N/128, M/128)
// ---------------------------------------------------------------------------
__global__ void gemm_nt_bias(const float* __restrict__ X, const float* __restrict__ W,
                             const float* __restrict__ bias, float* __restrict__ C,
                             int K, int N) {
    __shared__ float As[16][SM_PAD];
    __shared__ float Bs[16][SM_PAD];
    const int tid = threadIdx.x;                 // 256
    const int row0 = blockIdx.y * 128;
    const int col0 = blockIdx.x * 128;
    const int tr = tid >> 4, tc = tid & 15;

    float acc[8][8] = {};

    for (int kt = 0; kt < K; kt += 16) {
        #pragma unroll
        for (int i = 0; i < 2; i++) {
            int lin = tid + i * 256;
            int r = lin >> 2;
            int kq = (lin & 3) * 4;
            float4 xa = *(const float4*)&X[(size_t)(row0 + r) * K + kt + kq];
            float4 wb = *(const float4*)&W[(size_t)(col0 + r) * K + kt + kq];
            As[kq + 0][r] = xa.x; As[kq + 1][r] = xa.y;
            As[kq + 2][r] = xa.z; As[kq + 3][r] = xa.w;
            Bs[kq + 0][r] = wb.x; Bs[kq + 1][r] = wb.y;
            Bs[kq + 2][r] = wb.z; Bs[kq + 3][r] = wb.w;
        }
        __syncthreads();
        #pragma unroll
        for (int kk = 0; kk < 16; kk++) {
            float a[8], b[8];
            *(float4*)&a[0] = *(const float4*)&As[kk][tr * 8];
            *(float4*)&a[4] = *(const float4*)&As[kk][tr * 8 + 4];
            *(float4*)&b[0] = *(const float4*)&Bs[kk][tc * 8];
            *(float4*)&b[4] = *(const float4*)&Bs[kk][tc * 8 + 4];
            #pragma unroll
            for (int i = 0; i < 8; i++)
                #pragma unroll
                for (int j = 0; j < 8; j++)
                    acc[i][j] = fmaf(a[i], b[j], acc[i][j]);
        }
        __syncthreads();
    }

    #pragma unroll
    for (int i = 0; i < 8; i++) {
        const int r = row0 + tr * 8 + i;
        float* dst = &C[(size_t)r * N + col0 + tc * 8];
        #pragma unroll
        for (int j = 0; j < 8; j++)
            dst[j] = acc[i][j] + bias[col0 + tc * 8 + j];
    }
}

// ---------------------------------------------------------------------------
// A = scale * Q_h @ K_h^T per (b,h).  128x128 tile, K=64 (BK=16, 4 iters).
// grid = (16, 16, 32)
// ---------------------------------------------------------------------------
__global__ void qk128(const float* __restrict__ Q, const float* __restrict__ K,
                      float* __restrict__ A) {
    __shared__ float Qs[16][SM_PAD];
    __shared__ float Ks[16][SM_PAD];
    const int bh = blockIdx.z;
    const int b = bh >> 4, h = bh & 15;
    const int i0 = blockIdx.y * 128;
    const int j0 = blockIdx.x * 128;
    const int tid = threadIdx.x;
    const int tr = tid >> 4, tc = tid & 15;

    const float* Qb = Q + (size_t)b * Nc * Dc + h * HDc;
    const float* Kb = K + (size_t)b * Nc * Dc + h * HDc;

    float acc[8][8] = {};

    for (int kt = 0; kt < HDc; kt += 16) {
        #pragma unroll
        for (int i = 0; i < 2; i++) {
            int lin = tid + i * 256;
            int r = lin >> 2;
            int kq = (lin & 3) * 4;
            float4 qv = *(const float4*)&Qb[(size_t)(i0 + r) * Dc + kt + kq];
            float4 kv = *(const float4*)&Kb[(size_t)(j0 + r) * Dc + kt + kq];
            Qs[kq + 0][r] = qv.x; Qs[kq + 1][r] = qv.y;
            Qs[kq + 2][r] = qv.z; Qs[kq + 3][r] = qv.w;
            Ks[kq + 0][r] = kv.x; Ks[kq + 1][r] = kv.y;
            Ks[kq + 2][r] = kv.z; Ks[kq + 3][r] = kv.w;
        }
        __syncthreads();
        #pragma unroll
        for (int kk = 0; kk < 16; kk++) {
            float a[8], bv[8];
            *(float4*)&a[0]  = *(const float4*)&Qs[kk][tr * 8];
            *(float4*)&a[4]  = *(const float4*)&Qs[kk][tr * 8 + 4];
            *(float4*)&bv[0] = *(const float4*)&Ks[kk][tc * 8];
            *(float4*)&bv[4] = *(const float4*)&Ks[kk][tc * 8 + 4];
            #pragma unroll
            for (int i = 0; i < 8; i++)
                #pragma unroll
                for (int j = 0; j < 8; j++)
                    acc[i][j] = fmaf(a[i], bv[j], acc[i][j]);
        }
        __syncthreads();
    }

    const float scale = 0.125f;
    float* Ab = A + (size_t)bh * Nc * Nc;
    #pragma unroll
    for (int i = 0; i < 8; i++) {
        const int r = i0 + tr * 8 + i;
        float4 v0, v1;
        v0.x = acc[i][0] * scale; v0.y = acc[i][1] * scale;
        v0.z = acc[i][2] * scale; v0.w = acc[i][3] * scale;
        v1.x = acc[i][4] * scale; v1.y = acc[i][5] * scale;
        v1.z = acc[i][6] * scale; v1.w = acc[i][7] * scale;
        *(float4*)&Ab[(size_t)r * Nc + j0 + tc * 8]     = v0;
        *(float4*)&Ab[(size_t)r * Nc + j0 + tc * 8 + 4] = v1;
    }
}

// ---------------------------------------------------------------------------
// Row softmax in place, register-resident (8 floats/thread). 256 threads/row.
// ---------------------------------------------------------------------------
__global__ void softmax_kernel(float* __restrict__ A) {
    __shared__ float red[256];
    float4* p = (float4*)(A + (size_t)blockIdx.x * Nc);  // 512 float4
    const int t = threadIdx.x;

    float4 v0 = p[t];
    float4 v1 = p[t + 256];

    float m = fmaxf(fmaxf(fmaxf(v0.x, v0.y), fmaxf(v0.z, v0.w)),
                    fmaxf(fmaxf(v1.x, v1.y), fmaxf(v1.z, v1.w)));
    red[t] = m;
    __syncthreads();
    #pragma unroll
    for (int s = 128; s > 0; s >>= 1) {
        if (t < s) red[t] = fmaxf(red[t], red[t + s]);
        __syncthreads();
    }
    const float mx = red[0];
    __syncthreads();

    v0.x = __expf(v0.x - mx); v0.y = __expf(v0.y - mx);
    v0.z = __expf(v0.z - mx); v0.w = __expf(v0.w - mx);
    v1.x = __expf(v1.x - mx); v1.y = __expf(v1.y - mx);
    v1.z = __expf(v1.z - mx); v1.w = __expf(v1.w - mx);

    float sum = (v0.x + v0.y + v0.z + v0.w) + (v1.x + v1.y + v1.z + v1.w);
    red[t] = sum;
    __syncthreads();
    #pragma unroll
    for (int s = 128; s > 0; s >>= 1) {
        if (t < s) red[t] += red[t + s];
        __syncthreads();
    }
    const float inv = 1.f / red[0];

    v0.x *= inv; v0.y *= inv; v0.z *= inv; v0.w *= inv;
    v1.x *= inv; v1.y *= inv; v1.z *= inv; v1.w *= inv;
    p[t] = v0;
    p[t + 256] = v1;
}

// ---------------------------------------------------------------------------
// Vt = A @ V_h per (b,h), head-interleaved output. 128x64 tile, BK=16,
// 128 threads, 8x8 per thread. grid = (16, 32)
// ---------------------------------------------------------------------------
__global__ void av128(const float* __restrict__ A, const float* __restrict__ V,
                      float* __restrict__ Vt) {
    __shared__ float As[16][SM_PAD];
    __shared__ float Vs[16][64];
    const int bh = blockIdx.y;
    const int b = bh >> 4, h = bh & 15;
    const int i0 = blockIdx.x * 128;
    const int tid = threadIdx.x;                 // 128
    const int tr = tid >> 3, tc = tid & 7;       // 16 x 8

    const float* Ab = A + (size_t)bh * Nc * Nc;
    const float* Vb = V + (size_t)b * Nc * Dc + h * HDc;

    float acc[8][8] = {};

    for (int kt = 0; kt < Nc; kt += 16) {
        #pragma unroll
        for (int i = 0; i < 4; i++) {
            int lin = tid + i * 128;
            int r = lin >> 2;
            int kq = (lin & 3) * 4;
            float4 av = *(const float4*)&Ab[(size_t)(i0 + r) * Nc + kt + kq];
            As[kq + 0][r] = av.x; As[kq + 1][r] = av.y;
            As[kq + 2][r] = av.z; As[kq + 3][r] = av.w;
        }
        #pragma unroll
        for (int i = 0; i < 2; i++) {
            int lin = tid + i * 128;
            int r = lin >> 4;
            int cq = (lin & 15) * 4;
            *(float4*)&Vs[r][cq] = *(const float4*)&Vb[(size_t)(kt + r) * Dc + cq];
        }
        __syncthreads();
        #pragma unroll
        for (int kk = 0; kk < 16; kk++) {
            float a[8], bv[8];
            *(float4*)&a[0]  = *(const float4*)&As[kk][tr * 8];
            *(float4*)&a[4]  = *(const float4*)&As[kk][tr * 8 + 4];
            *(float4*)&bv[0] = *(const float4*)&Vs[kk][tc * 8];
            *(float4*)&bv[4] = *(const float4*)&Vs[kk][tc * 8 + 4];
            #pragma unroll
            for (int i = 0; i < 8; i++)
                #pragma unroll
                for (int j = 0; j < 8; j++)
                    acc[i][j] = fmaf(a[i], bv[j], acc[i][j]);
        }
        __syncthreads();
    }

    #pragma unroll
    for (int i = 0; i < 8; i++) {
        const int r = i0 + tr * 8 + i;
        float* dst = &Vt[(size_t)(b * Nc + r) * Dc + h * HDc + tc * 8];
        *(float4*)&dst[0] = *(float4*)&acc[i][0];
        *(float4*)&dst[4] = *(float4*)&acc[i][4];
    }
}

// ---------------------------------------------------------------------------
extern "C" void kernel_launch(void* const* d_in, const int* in_sizes, int n_in,
                              void* d_out, int out_size) {
    const float* query = (const float*)d_in[0];
    const float* key   = (const float*)d_in[1];
    const float* value = (const float*)d_in[2];
    const float* Wq = (const float*)d_in[3];
    const float* bq = (const float*)d_in[4];
    const float* Wk = (const float*)d_in[5];
    const float* bk = (const float*)d_in[6];
    const float* Wv = (const float*)d_in[7];
    const float* bv = (const float*)d_in[8];
    const float* Wo = (const float*)d_in[9];
    const float* bo = (const float*)d_in[10];

    float* out = (float*)d_out;              // [B, N, D]
    float* A   = (float*)d_out + OUT_ELEMS;  // [B, H, N, N]

    float* Q;  cudaGetSymbolAddress((void**)&Q,  g_Q);
    float* K;  cudaGetSymbolAddress((void**)&K,  g_K);
    float* V;  cudaGetSymbolAddress((void**)&V,  g_V);
    float* Vt; cudaGetSymbolAddress((void**)&Vt, g_Vt);

    // QKV projections: [4096,1024] @ [1024,1024]^T + b
    dim3 gProj(Dc / 128, MROWS / 128);
    gemm_nt_bias<<<gProj, 256>>>(query, Wq, bq, Q, Dc, Dc);
    gemm_nt_bias<<<gProj, 256>>>(key,   Wk, bk, K, Dc, Dc);
    gemm_nt_bias<<<gProj, 256>>>(value, Wv, bv, V, Dc, Dc);

    // A = scale * Q K^T
    dim3 gQK(Nc / 128, Nc / 128, BH);
    qk128<<<gQK, 256>>>(Q, K, A);

    // softmax rows (in place on A output)
    softmax_kernel<<<BH * Nc, 256>>>(A);

    // Vt = A V
    dim3 gAV(Nc / 128, BH);
    av128<<<gAV, 128>>>(A, V, Vt);

    // out = Vt @ Wo^T + bo
    gemm_nt_bias<<<gProj, 256>>>(Vt, Wo, bo, out, Dc, Dc);
}

// round 6
// speedup vs baseline: 2.1216x; 1.0017x over previous
#include <cuda_runtime.h>
#include <cuda_bf16.h>
#include <math.h>

// Problem constants
#define Bc 2
#define Nc 2048
#define Dc 1024
#define Hc 16
#define HDc 64
#define BH (Bc * Hc)          // 32
#define MROWS (Bc * Nc)       // 4096
#define OUT_ELEMS ((size_t)Bc * Nc * Dc)              // 4,194,304

// Scratch (static device memory — no runtime allocation)
__device__ float g_Q[MROWS * Dc];
__device__ float g_K[MROWS * Dc];
__device__ float g_V[MROWS * Dc];
__device__ float g_Vt[MROWS * Dc];

#define SM_PAD 132   // 128 + 4 pad, keeps float4 alignment (132*4 % 16 == 0)

// ---------------------------------------------------------------------------
// Projection GEMM: C[M,N] = X[M,K] @ W[N,K]^T + bias   (row-major)
// 128x128 tile, BK=16, 256 threads, 8x8 per thread.
// grid = (N/128, M/128)
// ---------------------------------------------------------------------------
__global__ void gemm_nt_bias(const float* __restrict__ X, const float* __restrict__ W,
                             const float* __restrict__ bias, float* __restrict__ C,
                             int K, int N) {
    __shared__ float As[16][SM_PAD];
    __shared__ float Bs[16][SM_PAD];
    const int tid = threadIdx.x;                 // 256
    const int row0 = blockIdx.y * 128;
    const int col0 = blockIdx.x * 128;
    const int tr = tid >> 4, tc = tid & 15;

    float acc[8][8] = {};

    for (int kt = 0; kt < K; kt += 16) {
        #pragma unroll
        for (int i = 0; i < 2; i++) {
            int lin = tid + i * 256;
            int r = lin >> 2;
            int kq = (lin & 3) * 4;
            float4 xa = *(const float4*)&X[(size_t)(row0 + r) * K + kt + kq];
            float4 wb = *(const float4*)&W[(size_t)(col0 + r) * K + kt + kq];
            As[kq + 0][r] = xa.x; As[kq + 1][r] = xa.y;
            As[kq + 2][r] = xa.z; As[kq + 3][r] = xa.w;
            Bs[kq + 0][r] = wb.x; Bs[kq + 1][r] = wb.y;
            Bs[kq + 2][r] = wb.z; Bs[kq + 3][r] = wb.w;
        }
        __syncthreads();
        #pragma unroll
        for (int kk = 0; kk < 16; kk++) {
            float a[8], b[8];
            *(float4*)&a[0] = *(const float4*)&As[kk][tr * 8];
            *(float4*)&a[4] = *(const float4*)&As[kk][tr * 8 + 4];
            *(float4*)&b[0] = *(const float4*)&Bs[kk][tc * 8];
            *(float4*)&b[4] = *(const float4*)&Bs[kk][tc * 8 + 4];
            #pragma unroll
            for (int i = 0; i < 8; i++)
                #pragma unroll
                for (int j = 0; j < 8; j++)
                    acc[i][j] = fmaf(a[i], b[j], acc[i][j]);
        }
        __syncthreads();
    }

    #pragma unroll
    for (int i = 0; i < 8; i++) {
        const int r = row0 + tr * 8 + i;
        float* dst = &C[(size_t)r * N + col0 + tc * 8];
        #pragma unroll
        for (int j = 0; j < 8; j++)
            dst[j] = acc[i][j] + bias[col0 + tc * 8 + j];
    }
}

// ---------------------------------------------------------------------------
// A = scale * Q_h @ K_h^T per (b,h).  128x128 tile, K=64 (BK=16, 4 iters).
// grid = (16, 16, 32)
// ---------------------------------------------------------------------------
__global__ void qk128(const float* __restrict__ Q, const float* __restrict__ K,
                      float* __restrict__ A) {
    __shared__ float Qs[16][SM_PAD];
    __shared__ float Ks[16][SM_PAD];
    const int bh = blockIdx.z;
    const int b = bh >> 4, h = bh & 15;
    const int i0 = blockIdx.y * 128;
    const int j0 = blockIdx.x * 128;
    const int tid = threadIdx.x;
    const int tr = tid >> 4, tc = tid & 15;

    const float* Qb = Q + (size_t)b * Nc * Dc + h * HDc;
    const float* Kb = K + (size_t)b * Nc * Dc + h * HDc;

    float acc[8][8] = {};

    for (int kt = 0; kt < HDc; kt += 16) {
        #pragma unroll
        for (int i = 0; i < 2; i++) {
            int lin = tid + i * 256;
            int r = lin >> 2;
            int kq = (lin & 3) * 4;
            float4 qv = *(const float4*)&Qb[(size_t)(i0 + r) * Dc + kt + kq];
            float4 kv = *(const float4*)&Kb[(size_t)(j0 + r) * Dc + kt + kq];
            Qs[kq + 0][r] = qv.x; Qs[kq + 1][r] = qv.y;
            Qs[kq + 2][r] = qv.z; Qs[kq + 3][r] = qv.w;
            Ks[kq + 0][r] = kv.x; Ks[kq + 1][r] = kv.y;
            Ks[kq + 2][r] = kv.z; Ks[kq + 3][r] = kv.w;
        }
        __syncthreads();
        #pragma unroll
        for (int kk = 0; kk < 16; kk++) {
            float a[8], bv[8];
            *(float4*)&a[0]  = *(const float4*)&Qs[kk][tr * 8];
            *(float4*)&a[4]  = *(const float4*)&Qs[kk][tr * 8 + 4];
            *(float4*)&bv[0] = *(const float4*)&Ks[kk][tc * 8];
            *(float4*)&bv[4] = *(const float4*)&Ks[kk][tc * 8 + 4];
            #pragma unroll
            for (int i = 0; i < 8; i++)
                #pragma unroll
                for (int j = 0; j < 8; j++)
                    acc[i][j] = fmaf(a[i], bv[j], acc[i][j]);
        }
        __syncthreads();
    }

    const float scale = 0.125f;
    float* Ab = A + (size_t)bh * Nc * Nc;
    #pragma unroll
    for (int i = 0; i < 8; i++) {
        const int r = i0 + tr * 8 + i;
        float4 v0, v1;
        v0.x = acc[i][0] * scale; v0.y = acc[i][1] * scale;
        v0.z = acc[i][2] * scale; v0.w = acc[i][3] * scale;
        v1.x = acc[i][4] * scale; v1.y = acc[i][5] * scale;
        v1.z = acc[i][6] * scale; v1.w = acc[i][7] * scale;
        *(float4*)&Ab[(size_t)r * Nc + j0 + tc * 8]     = v0;
        *(float4*)&Ab[(size_t)r * Nc + j0 + tc * 8 + 4] = v1;
    }
}

// ---------------------------------------------------------------------------
// Row softmax in place, register-resident (8 floats/thread). 256 threads/row.
// ---------------------------------------------------------------------------
__global__ void softmax_kernel(float* __restrict__ A) {
    __shared__ float red[256];
    float4* p = (float4*)(A + (size_t)blockIdx.x * Nc);  // 512 float4
    const int t = threadIdx.x;

    float4 v0 = p[t];
    float4 v1 = p[t + 256];

    float m = fmaxf(fmaxf(fmaxf(v0.x, v0.y), fmaxf(v0.z, v0.w)),
                    fmaxf(fmaxf(v1.x, v1.y), fmaxf(v1.z, v1.w)));
    red[t] = m;
    __syncthreads();
    #pragma unroll
    for (int s = 128; s > 0; s >>= 1) {
        if (t < s) red[t] = fmaxf(red[t], red[t + s]);
        __syncthreads();
    }
    const float mx = red[0];
    __syncthreads();

    v0.x = __expf(v0.x - mx); v0.y = __expf(v0.y - mx);
    v0.z = __expf(v0.z - mx); v0.w = __expf(v0.w - mx);
    v1.x = __expf(v1.x - mx); v1.y = __expf(v1.y - mx);
    v1.z = __expf(v1.z - mx); v1.w = __expf(v1.w - mx);

    float sum = (v0.x + v0.y + v0.z + v0.w) + (v1.x + v1.y + v1.z + v1.w);
    red[t] = sum;
    __syncthreads();
    #pragma unroll
    for (int s = 128; s > 0; s >>= 1) {
        if (t < s) red[t] += red[t + s];
        __syncthreads();
    }
    const float inv = 1.f / red[0];

    v0.x *= inv; v0.y *= inv; v0.z *= inv; v0.w *= inv;
    v1.x *= inv; v1.y *= inv; v1.z *= inv; v1.w *= inv;
    p[t] = v0;
    p[t + 256] = v1;
}

// ---------------------------------------------------------------------------
// Vt = A @ V_h per (b,h), head-interleaved output. 128x64 tile, BK=16,
// 128 threads, 8x8 per thread. grid = (16, 32)
// ---------------------------------------------------------------------------
__global__ void av128(const float* __restrict__ A, const float* __restrict__ V,
                      float* __restrict__ Vt) {
    __shared__ float As[16][SM_PAD];
    __shared__ float Vs[16][64];
    const int bh = blockIdx.y;
    const int b = bh >> 4, h = bh & 15;
    const int i0 = blockIdx.x * 128;
    const int tid = threadIdx.x;                 // 128
    const int tr = tid >> 3, tc = tid & 7;       // 16 x 8

    const float* Ab = A + (size_t)bh * Nc * Nc;
    const float* Vb = V + (size_t)b * Nc * Dc + h * HDc;

    float acc[8][8] = {};

    for (int kt = 0; kt < Nc; kt += 16) {
        #pragma unroll
        for (int i = 0; i < 4; i++) {
            int lin = tid + i * 128;
            int r = lin >> 2;
            int kq = (lin & 3) * 4;
            float4 av = *(const float4*)&Ab[(size_t)(i0 + r) * Nc + kt + kq];
            As[kq + 0][r] = av.x; As[kq + 1][r] = av.y;
            As[kq + 2][r] = av.z; As[kq + 3][r] = av.w;
        }
        #pragma unroll
        for (int i = 0; i < 2; i++) {
            int lin = tid + i * 128;
            int r = lin >> 4;
            int cq = (lin & 15) * 4;
            *(float4*)&Vs[r][cq] = *(const float4*)&Vb[(size_t)(kt + r) * Dc + cq];
        }
        __syncthreads();
        #pragma unroll
        for (int kk = 0; kk < 16; kk++) {
            float a[8], bv[8];
            *(float4*)&a[0]  = *(const float4*)&As[kk][tr * 8];
            *(float4*)&a[4]  = *(const float4*)&As[kk][tr * 8 + 4];
            *(float4*)&bv[0] = *(const float4*)&Vs[kk][tc * 8];
            *(float4*)&bv[4] = *(const float4*)&Vs[kk][tc * 8 + 4];
            #pragma unroll
            for (int i = 0; i < 8; i++)
                #pragma unroll
                for (int j = 0; j < 8; j++)
                    acc[i][j] = fmaf(a[i], bv[j], acc[i][j]);
        }
        __syncthreads();
    }

    #pragma unroll
    for (int i = 0; i < 8; i++) {
        const int r = i0 + tr * 8 + i;
        float* dst = &Vt[(size_t)(b * Nc + r) * Dc + h * HDc + tc * 8];
        *(float4*)&dst[0] = *(float4*)&acc[i][0];
        *(float4*)&dst[4] = *(float4*)&acc[i][4];
    }
}

// ---------------------------------------------------------------------------
extern "C" void kernel_launch(void* const* d_in, const int* in_sizes, int n_in,
                              void* d_out, int out_size) {
    const float* query = (const float*)d_in[0];
    const float* key   = (const float*)d_in[1];
    const float* value = (const float*)d_in[2];
    const float* Wq = (const float*)d_in[3];
    const float* bq = (const float*)d_in[4];
    const float* Wk = (const float*)d_in[5];
    const float* bk = (const float*)d_in[6];
    const float* Wv = (const float*)d_in[7];
    const float* bv = (const float*)d_in[8];
    const float* Wo = (const float*)d_in[9];
    const float* bo = (const float*)d_in[10];

    float* out = (float*)d_out;              // [B, N, D]
    float* A   = (float*)d_out + OUT_ELEMS;  // [B, H, N, N]

    float* Q;  cudaGetSymbolAddress((void**)&Q,  g_Q);
    float* K;  cudaGetSymbolAddress((void**)&K,  g_K);
    float* V;  cudaGetSymbolAddress((void**)&V,  g_V);
    float* Vt; cudaGetSymbolAddress((void**)&Vt, g_Vt);

    // QKV projections: [4096,1024] @ [1024,1024]^T + b
    dim3 gProj(Dc / 128, MROWS / 128);
    gemm_nt_bias<<<gProj, 256>>>(query, Wq, bq, Q, Dc, Dc);
    gemm_nt_bias<<<gProj, 256>>>(key,   Wk, bk, K, Dc, Dc);
    gemm_nt_bias<<<gProj, 256>>>(value, Wv, bv, V, Dc, Dc);

    // A = scale * Q K^T
    dim3 gQK(Nc / 128, Nc / 128, BH);
    qk128<<<gQK, 256>>>(Q, K, A);

    // softmax rows (in place on A output)
    softmax_kernel<<<BH * Nc, 256>>>(A);

    // Vt = A V
    dim3 gAV(Nc / 128, BH);
    av128<<<gAV, 128>>>(A, V, Vt);

    // out = Vt @ Wo^T + bo
    gemm_nt_bias<<<gProj, 256>>>(Vt, Wo, bo, out, Dc, Dc);
}